// round 1
// baseline (speedup 1.0000x reference)
#include <cuda_runtime.h>
#include <cuda_bf16.h>

// Problem constants
#define B_DIM 64
#define J_DIM 24
#define T_DIM 2048
#define T4 (T_DIM / 4)
#define LAMBDA_VEL 0.2
#define LAMBDA_FOOT 0.1
#define CONTACT_THRESH 0.05f

// accumulators: [0]=recon_sum, [1]=vel_sum, [2]=foot_loss_sum, [3]=cw_sum
__device__ double g_acc[4];

__global__ void k_zero() {
    if (threadIdx.x < 4) g_acc[threadIdx.x] = 0.0;
}

// One pass over pred/target: recon = sum d^2, vel = sum (d[t+1]-d[t])^2 within rows of T
__global__ void __launch_bounds__(256) k_main(const float* __restrict__ pred,
                                              const float* __restrict__ target,
                                              int n4) {
    float recon = 0.0f, vel = 0.0f;
    const float4* p4 = (const float4*)pred;
    const float4* t4 = (const float4*)target;

    for (int i = blockIdx.x * blockDim.x + threadIdx.x; i < n4;
         i += gridDim.x * blockDim.x) {
        float4 p = p4[i];
        float4 t = t4[i];
        float d0 = p.x - t.x;
        float d1 = p.y - t.y;
        float d2 = p.z - t.z;
        float d3 = p.w - t.w;
        recon += d0 * d0 + d1 * d1 + d2 * d2 + d3 * d3;
        float v01 = d1 - d0, v12 = d2 - d1, v23 = d3 - d2;
        float v = v01 * v01 + v12 * v12 + v23 * v23;
        // neighbor across float4 boundary (same T-row only)
        int col4 = i & (T4 - 1);           // i % 512
        if (col4 != T4 - 1) {
            int e = i * 4 + 4;
            float dn = pred[e] - target[e];  // L1/L2 hit (loaded by neighbor thread)
            float v3n = dn - d3;
            v += v3n * v3n;
        }
        vel += v;
    }

    // warp reduce
    #pragma unroll
    for (int o = 16; o; o >>= 1) {
        recon += __shfl_down_sync(0xFFFFFFFFu, recon, o);
        vel   += __shfl_down_sync(0xFFFFFFFFu, vel, o);
    }
    if ((threadIdx.x & 31) == 0) {
        atomicAdd(&g_acc[0], (double)recon);
        atomicAdd(&g_acc[1], (double)vel);
    }
}

__device__ __forceinline__ float sigmoidf_fast(float x) {
    // 1/(1+exp(-x)); expf(inf) -> inf -> result 0: safe for large |x|
    return 1.0f / (1.0f + __expf(-x));
}

// One block per (b, foot) pair. grid = B*4.
__global__ void __launch_bounds__(256) k_foot(const float* __restrict__ jp) {
    const int foot_map[4] = {7, 8, 10, 11};
    int b = blockIdx.x >> 2;
    int f = blockIdx.x & 3;
    int j = foot_map[f];

    const float* base = jp + ((size_t)(b * J_DIM + j) * 3) * T_DIM;
    const float* xr = base;
    const float* yr = base + T_DIM;
    const float* zr = base + 2 * T_DIM;

    float lsum = 0.0f, csum = 0.0f;

    for (int c4 = threadIdx.x; c4 < T4; c4 += blockDim.x) {
        int col = c4 * 4;
        float4 x = ((const float4*)xr)[c4];
        float4 y = ((const float4*)yr)[c4];
        float4 z = ((const float4*)zr)[c4];
        bool has_next = (col + 4 < T_DIM);
        float xs[5] = {x.x, x.y, x.z, x.w, has_next ? xr[col + 4] : 0.0f};
        float ys[5] = {y.x, y.y, y.z, y.w, has_next ? yr[col + 4] : 0.0f};
        float zs[5] = {z.x, z.y, z.z, z.w, has_next ? zr[col + 4] : 0.0f};

        int kmax = has_next ? 4 : 3;  // t < T-1 constraint
        #pragma unroll
        for (int k = 0; k < 4; k++) {
            if (k < kmax) {
                float w0 = sigmoidf_fast((CONTACT_THRESH - ys[k])     * 20.0f);
                float w1 = sigmoidf_fast((CONTACT_THRESH - ys[k + 1]) * 20.0f);
                float cw = 0.5f * (w0 + w1);
                float dx = xs[k + 1] - xs[k];
                float dz = zs[k + 1] - zs[k];
                lsum += (dx * dx + dz * dz) * cw;
                csum += cw;
            }
        }
    }

    #pragma unroll
    for (int o = 16; o; o >>= 1) {
        lsum += __shfl_down_sync(0xFFFFFFFFu, lsum, o);
        csum += __shfl_down_sync(0xFFFFFFFFu, csum, o);
    }
    if ((threadIdx.x & 31) == 0) {
        atomicAdd(&g_acc[2], (double)lsum);
        atomicAdd(&g_acc[3], (double)csum);
    }
}

__global__ void k_final(float* __restrict__ out) {
    const double N1 = (double)B_DIM * J_DIM * 6 * T_DIM;          // recon count
    const double N2 = (double)B_DIM * J_DIM * 6 * (T_DIM - 1);    // vel count
    double recon = g_acc[0] / N1;
    double vel = g_acc[1] / N2;
    double foot = g_acc[2] / (g_acc[3] + 1e-08);
    out[0] = (float)(recon + LAMBDA_VEL * vel + LAMBDA_FOOT * foot);
}

extern "C" void kernel_launch(void* const* d_in, const int* in_sizes, int n_in,
                              void* d_out, int out_size) {
    const float* pred   = (const float*)d_in[0];
    const float* target = (const float*)d_in[1];
    const float* jp     = (const float*)d_in[2];
    float* out = (float*)d_out;

    int n4 = (B_DIM * J_DIM * 6 * T_DIM) / 4;  // 4,718,592

    k_zero<<<1, 32>>>();
    k_main<<<1184, 256>>>(pred, target, n4);
    k_foot<<<B_DIM * 4, 256>>>(jp);
    k_final<<<1, 1>>>(out);
}

// round 2
// speedup vs baseline: 1.8341x; 1.8341x over previous
#include <cuda_runtime.h>
#include <cuda_bf16.h>

#define B_DIM 64
#define J_DIM 24
#define T_DIM 2048
#define T4 (T_DIM / 4)
#define LAMBDA_VEL 0.2
#define LAMBDA_FOOT 0.1
#define CONTACT_THRESH 0.05f

#define GRID_BLOCKS 1184   // 148 SMs * 8 blocks of 256 -> full occupancy
#define NTHREADS 256

// accumulators: [0]=recon, [1]=vel, [2]=foot_loss, [3]=cw_sum  (zero-init, reset by last block)
__device__ double g_acc[4];
__device__ unsigned int g_done;   // zero-init, reset by last block

__device__ __forceinline__ float sigmoidf_fast(float x) {
    return 1.0f / (1.0f + __expf(-x));
}

__global__ void __launch_bounds__(NTHREADS) k_fused(const float* __restrict__ pred,
                                                    const float* __restrict__ target,
                                                    const float* __restrict__ jp,
                                                    float* __restrict__ out) {
    const int tid = blockIdx.x * blockDim.x + threadIdx.x;
    const int stride = gridDim.x * blockDim.x;

    // ---------------- main: recon + vel over pred/target ----------------
    float recon = 0.0f, vel = 0.0f;
    {
        const int n4 = (B_DIM * J_DIM * 6 * T_DIM) / 4;   // 4,718,592
        const float4* p4 = (const float4*)pred;
        const float4* t4 = (const float4*)target;
        for (int i = tid; i < n4; i += stride) {
            float4 p = p4[i];
            float4 t = t4[i];
            float d0 = p.x - t.x;
            float d1 = p.y - t.y;
            float d2 = p.z - t.z;
            float d3 = p.w - t.w;
            recon += d0 * d0 + d1 * d1 + d2 * d2 + d3 * d3;
            float v01 = d1 - d0, v12 = d2 - d1, v23 = d3 - d2;
            float v = v01 * v01 + v12 * v12 + v23 * v23;
            if ((i & (T4 - 1)) != T4 - 1) {               // cross-float4 neighbor, same T row
                int e = i * 4 + 4;
                float dn = pred[e] - target[e];           // L1/L2 hit
                float v3n = dn - d3;
                v += v3n * v3n;
            }
            vel += v;
        }
    }

    // ---------------- foot contact loss ----------------
    float lsum = 0.0f, csum = 0.0f;
    {
        const int foot_map[4] = {7, 8, 10, 11};
        const int nfoot = B_DIM * 4 * T4;                 // 256 rows * 512 groups = 131072
        for (int idx = tid; idx < nfoot; idx += stride) {
            int c4 = idx & (T4 - 1);
            int row = idx >> 9;                           // / T4
            int b = row >> 2;
            int j = foot_map[row & 3];
            const float* base = jp + ((size_t)(b * J_DIM + j) * 3) * T_DIM;
            const float* xr = base;
            const float* yr = base + T_DIM;
            const float* zr = base + 2 * T_DIM;

            int col = c4 * 4;
            float4 x = ((const float4*)xr)[c4];
            float4 y = ((const float4*)yr)[c4];
            float4 z = ((const float4*)zr)[c4];
            bool has_next = (col + 4 < T_DIM);
            float xs[5] = {x.x, x.y, x.z, x.w, has_next ? xr[col + 4] : 0.0f};
            float ys[5] = {y.x, y.y, y.z, y.w, has_next ? yr[col + 4] : 0.0f};
            float zs[5] = {z.x, z.y, z.z, z.w, has_next ? zr[col + 4] : 0.0f};

            int kmax = has_next ? 4 : 3;
            #pragma unroll
            for (int k = 0; k < 4; k++) {
                if (k < kmax) {
                    float w0 = sigmoidf_fast((CONTACT_THRESH - ys[k])     * 20.0f);
                    float w1 = sigmoidf_fast((CONTACT_THRESH - ys[k + 1]) * 20.0f);
                    float cw = 0.5f * (w0 + w1);
                    float dx = xs[k + 1] - xs[k];
                    float dz = zs[k + 1] - zs[k];
                    lsum += (dx * dx + dz * dz) * cw;
                    csum += cw;
                }
            }
        }
    }

    // ---------------- block reduction ----------------
    __shared__ float s0[8], s1[8], s2[8], s3[8];
    #pragma unroll
    for (int o = 16; o; o >>= 1) {
        recon += __shfl_down_sync(0xFFFFFFFFu, recon, o);
        vel   += __shfl_down_sync(0xFFFFFFFFu, vel, o);
        lsum  += __shfl_down_sync(0xFFFFFFFFu, lsum, o);
        csum  += __shfl_down_sync(0xFFFFFFFFu, csum, o);
    }
    int warp = threadIdx.x >> 5;
    if ((threadIdx.x & 31) == 0) {
        s0[warp] = recon; s1[warp] = vel; s2[warp] = lsum; s3[warp] = csum;
    }
    __syncthreads();
    if (threadIdx.x == 0) {
        float r = 0, v = 0, l = 0, c = 0;
        #pragma unroll
        for (int w = 0; w < NTHREADS / 32; w++) { r += s0[w]; v += s1[w]; l += s2[w]; c += s3[w]; }
        atomicAdd(&g_acc[0], (double)r);
        atomicAdd(&g_acc[1], (double)v);
        atomicAdd(&g_acc[2], (double)l);
        atomicAdd(&g_acc[3], (double)c);
        __threadfence();
        unsigned int done = atomicAdd(&g_done, 1u);
        if (done == gridDim.x - 1) {
            // last block: finalize, write out, reset state for next graph replay
            const double N1 = (double)B_DIM * J_DIM * 6 * T_DIM;
            const double N2 = (double)B_DIM * J_DIM * 6 * (T_DIM - 1);
            double recon_m = g_acc[0] / N1;
            double vel_m   = g_acc[1] / N2;
            double foot_m  = g_acc[2] / (g_acc[3] + 1e-08);
            out[0] = (float)(recon_m + LAMBDA_VEL * vel_m + LAMBDA_FOOT * foot_m);
            g_acc[0] = 0.0; g_acc[1] = 0.0; g_acc[2] = 0.0; g_acc[3] = 0.0;
            g_done = 0u;
        }
    }
}

extern "C" void kernel_launch(void* const* d_in, const int* in_sizes, int n_in,
                              void* d_out, int out_size) {
    const float* pred   = (const float*)d_in[0];
    const float* target = (const float*)d_in[1];
    const float* jp     = (const float*)d_in[2];
    float* out = (float*)d_out;
    k_fused<<<GRID_BLOCKS, NTHREADS>>>(pred, target, jp, out);
}

// round 3
// speedup vs baseline: 2.0000x; 1.0904x over previous
#include <cuda_runtime.h>
#include <cuda_bf16.h>

#define B_DIM 64
#define J_DIM 24
#define T_DIM 2048
#define T4 (T_DIM / 4)
#define LAMBDA_VEL 0.2
#define LAMBDA_FOOT 0.1
#define CONTACT_THRESH 0.05f

#define GRID_BLOCKS 1152   // 1152*256 = 294912 threads; n4 / threads = 16 exactly
#define NTHREADS 256
#define MAIN_ITERS 16

// accumulators: [0]=recon, [1]=vel, [2]=foot_loss, [3]=cw_sum  (zero-init, reset by last block)
__device__ double g_acc[4];
__device__ unsigned int g_done;

__device__ __forceinline__ float sigmoidf_fast(float x) {
    return 1.0f / (1.0f + __expf(-x));
}

__global__ void __launch_bounds__(NTHREADS) k_fused(const float* __restrict__ pred,
                                                    const float* __restrict__ target,
                                                    const float* __restrict__ jp,
                                                    float* __restrict__ out) {
    const int tid = blockIdx.x * blockDim.x + threadIdx.x;
    const int stride = GRID_BLOCKS * NTHREADS;
    const int lane = threadIdx.x & 31;

    // ---------------- main: recon + vel over pred/target ----------------
    float recon = 0.0f, vel = 0.0f;
    {
        const float4* p4 = (const float4*)pred;
        const float4* t4 = (const float4*)target;

        #pragma unroll
        for (int k = 0; k < MAIN_ITERS; k += 2) {
            int i0 = tid + k * stride;
            int i1 = i0 + stride;
            float4 p0 = __ldcs(p4 + i0);
            float4 t0 = __ldcs(t4 + i0);
            float4 p1 = __ldcs(p4 + i1);
            float4 t1 = __ldcs(t4 + i1);

            // ---- element 0 ----
            {
                float d0 = p0.x - t0.x, d1 = p0.y - t0.y, d2 = p0.z - t0.z, d3 = p0.w - t0.w;
                recon += d0 * d0 + d1 * d1 + d2 * d2 + d3 * d3;
                float v01 = d1 - d0, v12 = d2 - d1, v23 = d3 - d2;
                float v = v01 * v01 + v12 * v12 + v23 * v23;
                float dn = __shfl_down_sync(0xFFFFFFFFu, d0, 1);   // lane l+1's d0 = our t+4
                bool valid = (i0 & (T4 - 1)) != (T4 - 1);
                if (lane == 31 && valid) {
                    int e = i0 * 4 + 4;
                    dn = pred[e] - target[e];
                }
                if (valid) {
                    float v3n = dn - d3;
                    v += v3n * v3n;
                }
                vel += v;
            }
            // ---- element 1 ----
            {
                float d0 = p1.x - t1.x, d1 = p1.y - t1.y, d2 = p1.z - t1.z, d3 = p1.w - t1.w;
                recon += d0 * d0 + d1 * d1 + d2 * d2 + d3 * d3;
                float v01 = d1 - d0, v12 = d2 - d1, v23 = d3 - d2;
                float v = v01 * v01 + v12 * v12 + v23 * v23;
                float dn = __shfl_down_sync(0xFFFFFFFFu, d0, 1);
                bool valid = (i1 & (T4 - 1)) != (T4 - 1);
                if (lane == 31 && valid) {
                    int e = i1 * 4 + 4;
                    dn = pred[e] - target[e];
                }
                if (valid) {
                    float v3n = dn - d3;
                    v += v3n * v3n;
                }
                vel += v;
            }
        }
    }

    // ---------------- foot contact loss ----------------
    float lsum = 0.0f, csum = 0.0f;
    {
        const int foot_map[4] = {7, 8, 10, 11};
        const int nfoot = B_DIM * 4 * T4;                 // 131072 < total threads
        if (tid < nfoot) {
            int c4 = tid & (T4 - 1);
            int row = tid >> 9;
            int b = row >> 2;
            int j = foot_map[row & 3];
            const float* base = jp + ((size_t)(b * J_DIM + j) * 3) * T_DIM;
            const float* xr = base;
            const float* yr = base + T_DIM;
            const float* zr = base + 2 * T_DIM;

            int col = c4 * 4;
            float4 x = ((const float4*)xr)[c4];
            float4 y = ((const float4*)yr)[c4];
            float4 z = ((const float4*)zr)[c4];
            bool has_next = (col + 4 < T_DIM);
            float xs[5] = {x.x, x.y, x.z, x.w, has_next ? xr[col + 4] : 0.0f};
            float ys[5] = {y.x, y.y, y.z, y.w, has_next ? yr[col + 4] : 0.0f};
            float zs[5] = {z.x, z.y, z.z, z.w, has_next ? zr[col + 4] : 0.0f};

            int kmax = has_next ? 4 : 3;
            #pragma unroll
            for (int k = 0; k < 4; k++) {
                if (k < kmax) {
                    float w0 = sigmoidf_fast((CONTACT_THRESH - ys[k])     * 20.0f);
                    float w1 = sigmoidf_fast((CONTACT_THRESH - ys[k + 1]) * 20.0f);
                    float cw = 0.5f * (w0 + w1);
                    float dx = xs[k + 1] - xs[k];
                    float dz = zs[k + 1] - zs[k];
                    lsum += (dx * dx + dz * dz) * cw;
                    csum += cw;
                }
            }
        }
    }

    // ---------------- block reduction ----------------
    __shared__ float s0[8], s1[8], s2[8], s3[8];
    #pragma unroll
    for (int o = 16; o; o >>= 1) {
        recon += __shfl_down_sync(0xFFFFFFFFu, recon, o);
        vel   += __shfl_down_sync(0xFFFFFFFFu, vel, o);
        lsum  += __shfl_down_sync(0xFFFFFFFFu, lsum, o);
        csum  += __shfl_down_sync(0xFFFFFFFFu, csum, o);
    }
    int warp = threadIdx.x >> 5;
    if ((threadIdx.x & 31) == 0) {
        s0[warp] = recon; s1[warp] = vel; s2[warp] = lsum; s3[warp] = csum;
    }
    __syncthreads();
    if (threadIdx.x == 0) {
        float r = 0, v = 0, l = 0, c = 0;
        #pragma unroll
        for (int w = 0; w < NTHREADS / 32; w++) { r += s0[w]; v += s1[w]; l += s2[w]; c += s3[w]; }
        atomicAdd(&g_acc[0], (double)r);
        atomicAdd(&g_acc[1], (double)v);
        atomicAdd(&g_acc[2], (double)l);
        atomicAdd(&g_acc[3], (double)c);
        __threadfence();
        unsigned int done = atomicAdd(&g_done, 1u);
        if (done == gridDim.x - 1) {
            const double N1 = (double)B_DIM * J_DIM * 6 * T_DIM;
            const double N2 = (double)B_DIM * J_DIM * 6 * (T_DIM - 1);
            double recon_m = g_acc[0] / N1;
            double vel_m   = g_acc[1] / N2;
            double foot_m  = g_acc[2] / (g_acc[3] + 1e-08);
            out[0] = (float)(recon_m + LAMBDA_VEL * vel_m + LAMBDA_FOOT * foot_m);
            g_acc[0] = 0.0; g_acc[1] = 0.0; g_acc[2] = 0.0; g_acc[3] = 0.0;
            g_done = 0u;
        }
    }
}

extern "C" void kernel_launch(void* const* d_in, const int* in_sizes, int n_in,
                              void* d_out, int out_size) {
    const float* pred   = (const float*)d_in[0];
    const float* target = (const float*)d_in[1];
    const float* jp     = (const float*)d_in[2];
    float* out = (float*)d_out;
    k_fused<<<GRID_BLOCKS, NTHREADS>>>(pred, target, jp, out);
}